// round 4
// baseline (speedup 1.0000x reference)
#include <cuda_runtime.h>

#define TT 35
#define CC 4
#define CIN 7
#define HH 64
#define BN_EPS 1e-5
#define NB 296          // stats grid size (fixed)

// per-block partial moments: [stat][block], stat = 28 upper-tri M + 7 S1
__device__ float g_part[35][NB];
__device__ unsigned g_ticket;          // zero-init at load; last block resets -> replay-safe
__device__ float g_WpT[CIN * HH];      // BN-folded weights, TRANSPOSED [k][j]
__device__ float g_bp[HH];

__device__ __forceinline__ void accum_row(float* acc, float4 r, float mx, float my, float mz) {
    float a[7];
    a[0] = r.x; a[1] = r.y; a[2] = r.z; a[3] = r.w;
    a[4] = r.x - mx; a[5] = r.y - my; a[6] = r.z - mz;
    int idx = 0;
#pragma unroll
    for (int k = 0; k < 7; k++) {
#pragma unroll
        for (int l = 0; l <= k; l++) {
            acc[idx] = fmaf(a[k], a[l], acc[idx]);
            idx++;
        }
    }
#pragma unroll
    for (int k = 0; k < 7; k++) acc[28 + k] += a[k];
}

// Fused stats + BN-fold. Each warp owns voxels in a grid-stride chain and
// accumulates the 35 moment scalars; block partials go to g_part (plain
// stores, no global zeroing needed). The last block (atomic ticket) reduces
// the partials and folds BN into the linear layer in fp64.
__global__ void stats_fold_kernel(const float* __restrict__ vox, int N,
                                  const float* __restrict__ Wm, const float* __restrict__ b,
                                  const float* __restrict__ gamma, const float* __restrict__ beta) {
    const unsigned FULL = 0xffffffffu;
    int lane = threadIdx.x & 31;
    int warpId = (blockIdx.x * blockDim.x + threadIdx.x) >> 5;
    int nWarps = (gridDim.x * blockDim.x) >> 5;

    __shared__ float bacc[35];
    if (threadIdx.x < 35) bacc[threadIdx.x] = 0.f;
    __syncthreads();

    float acc[35];
#pragma unroll
    for (int i = 0; i < 35; i++) acc[i] = 0.f;

    for (int n = warpId; n < N; n += nWarps) {
        const float4* vp = (const float4*)(vox + (size_t)n * (TT * CC));
        float4 r0 = vp[lane];                       // rows 0..31
        float4 r1 = make_float4(0.f, 0.f, 0.f, 0.f);
        bool has2 = (lane < (TT - 32));             // lanes 0..2 take rows 32..34
        if (has2) r1 = vp[lane + 32];

        float sx = r0.x + r1.x;
        float sy = r0.y + r1.y;
        float sz = r0.z + r1.z;
        float rs0 = r0.x + r0.y + r0.z + r0.w;
        float cnt = (rs0 != 0.f) ? 1.f : 0.f;
        if (has2) {
            float rs1 = r1.x + r1.y + r1.z + r1.w;
            if (rs1 != 0.f) cnt += 1.f;
        }
#pragma unroll
        for (int o = 16; o; o >>= 1) {
            sx  += __shfl_down_sync(FULL, sx, o);
            sy  += __shfl_down_sync(FULL, sy, o);
            sz  += __shfl_down_sync(FULL, sz, o);
            cnt += __shfl_down_sync(FULL, cnt, o);
        }
        sx  = __shfl_sync(FULL, sx, 0);
        sy  = __shfl_sync(FULL, sy, 0);
        sz  = __shfl_sync(FULL, sz, 0);
        cnt = __shfl_sync(FULL, cnt, 0);

        float inv = 1.f / cnt;
        float mx = sx * inv, my = sy * inv, mz = sz * inv;

        accum_row(acc, r0, mx, my, mz);
        if (has2) accum_row(acc, r1, mx, my, mz);
    }

#pragma unroll
    for (int i = 0; i < 35; i++) {
        float v = acc[i];
#pragma unroll
        for (int o = 16; o; o >>= 1) v += __shfl_down_sync(FULL, v, o);
        if (lane == 0) atomicAdd(&bacc[i], v);
    }
    __syncthreads();

    if (threadIdx.x < 35) g_part[threadIdx.x][blockIdx.x] = bacc[threadIdx.x];
    __threadfence();

    __shared__ bool s_last;
    if (threadIdx.x == 0) {
        unsigned t = atomicAdd(&g_ticket, 1u);
        s_last = (t == gridDim.x - 1);
    }
    __syncthreads();
    if (!s_last) return;

    // ---- last block: reduce partials + fold BN into W,b ----
    if (threadIdx.x == 0) g_ticket = 0;   // reset for next graph replay
    __threadfence();                       // acquire: order partial reads after ticket

    __shared__ float sstat[35];
    if (threadIdx.x < 35) {
        float s = 0.f;
        const float* p = g_part[threadIdx.x];
#pragma unroll 8
        for (int bb = 0; bb < NB; bb++) s += __ldcg(&p[bb]);
        sstat[threadIdx.x] = s;
    }
    __syncthreads();

    int j = threadIdx.x;
    if (j >= HH) return;

    double M[28], S1[7];
#pragma unroll
    for (int i = 0; i < 28; i++) M[i] = (double)sstat[i];
#pragma unroll
    for (int k = 0; k < 7; k++) S1[k] = (double)sstat[28 + k];

    double w[7];
#pragma unroll
    for (int k = 0; k < 7; k++) w[k] = (double)Wm[j * CIN + k];
    double bj = (double)b[j];

    double dotWS = 0.0;
#pragma unroll
    for (int k = 0; k < 7; k++) dotWS += w[k] * S1[k];

    double quad = 0.0;
    int idx = 0;
#pragma unroll
    for (int k = 0; k < 7; k++) {
#pragma unroll
        for (int l = 0; l <= k; l++) {
            double term = w[k] * w[l] * M[idx];
            quad += (l == k) ? term : 2.0 * term;
            idx++;
        }
    }

    double Nt = (double)N * (double)TT;
    double sumx  = dotWS + Nt * bj;
    double sumxx = quad + 2.0 * bj * dotWS + Nt * bj * bj;
    double mu  = sumx / Nt;
    double var = sumxx / Nt - mu * mu;
    double inv = 1.0 / sqrt(var + (double)BN_EPS);
    double a = (double)gamma[j] * inv;

#pragma unroll
    for (int k = 0; k < 7; k++) g_WpT[k * HH + j] = (float)(a * w[k]);
    g_bp[j] = (float)((double)beta[j] + a * (bj - mu));
}

__device__ __forceinline__ void fma4(float4& v, const float4 w, float a) {
    v.x = fmaf(w.x, a, v.x);
    v.y = fmaf(w.y, a, v.y);
    v.z = fmaf(w.z, a, v.z);
    v.w = fmaf(w.w, a, v.w);
}

// One 64-thread block per voxel. Thread (g = tid&15, tq = tid>>4) computes
// output channels 4g..4g+3 for rows t ≡ tq (mod 4), with BN-folded weights in
// registers, and stores float4 DIRECTLY to gmem (no smem staging). The
// per-channel max is a tiny 4-way smem reduction; the max-half is streamed
// from one register float4.
__global__ __launch_bounds__(64) void main_kernel(const float* __restrict__ vox,
                                                  float* __restrict__ out) {
    __shared__ float4 srow[TT];
    __shared__ float  swpT[CIN][HH];
    __shared__ float  sbp[HH];
    __shared__ float4 spmax[4][16];
    __shared__ float4 smaxf[16];
    __shared__ float  smean[3];

    int n = blockIdx.x;
    int tid = threadIdx.x;

    // stage folded weights / bias (coalesced)
#pragma unroll
    for (int k = 0; k < CIN; k++) swpT[k][tid] = g_WpT[k * HH + tid];
    sbp[tid] = g_bp[tid];

    const float4* vp = (const float4*)(vox + (size_t)n * (TT * CC));
    if (tid < TT) srow[tid] = vp[tid];
    __syncthreads();

    // warp0: mean of channels 0..2 over non-empty rows
    if (tid < 32) {
        const unsigned FULL = 0xffffffffu;
        float4 a = srow[tid];
        float sx = a.x, sy = a.y, sz = a.z;
        float rs = a.x + a.y + a.z + a.w;
        float cnt = (rs != 0.f) ? 1.f : 0.f;
        if (tid < TT - 32) {
            float4 b2 = srow[tid + 32];
            sx += b2.x; sy += b2.y; sz += b2.z;
            float rs2 = b2.x + b2.y + b2.z + b2.w;
            if (rs2 != 0.f) cnt += 1.f;
        }
#pragma unroll
        for (int o = 16; o; o >>= 1) {
            sx  += __shfl_down_sync(FULL, sx, o);
            sy  += __shfl_down_sync(FULL, sy, o);
            sz  += __shfl_down_sync(FULL, sz, o);
            cnt += __shfl_down_sync(FULL, cnt, o);
        }
        if (tid == 0) {
            float inv = 1.f / cnt;
            smean[0] = sx * inv; smean[1] = sy * inv; smean[2] = sz * inv;
        }
    }
    __syncthreads();

    int g = tid & 15, tq = tid >> 4;
    float4 w0 = *(const float4*)&swpT[0][g * 4];
    float4 w1 = *(const float4*)&swpT[1][g * 4];
    float4 w2 = *(const float4*)&swpT[2][g * 4];
    float4 w3 = *(const float4*)&swpT[3][g * 4];
    float4 w4 = *(const float4*)&swpT[4][g * 4];
    float4 w5 = *(const float4*)&swpT[5][g * 4];
    float4 w6 = *(const float4*)&swpT[6][g * 4];
    float4 bias = *(const float4*)&sbp[g * 4];
    float mx = smean[0], my = smean[1], mz = smean[2];

    float* ob = out + (size_t)n * (TT * 2 * HH) + g * 4;
    float4 pmax = make_float4(0.f, 0.f, 0.f, 0.f);   // ReLU output >= 0

#pragma unroll
    for (int i = 0; i < 9; i++) {
        int t = tq + i * 4;
        if (t < TT) {
            float4 r = srow[t];
            float4 v = bias;
            fma4(v, w0, r.x);
            fma4(v, w1, r.y);
            fma4(v, w2, r.z);
            fma4(v, w3, r.w);
            fma4(v, w4, r.x - mx);
            fma4(v, w5, r.y - my);
            fma4(v, w6, r.z - mz);
            v.x = fmaxf(v.x, 0.f); v.y = fmaxf(v.y, 0.f);
            v.z = fmaxf(v.z, 0.f); v.w = fmaxf(v.w, 0.f);
            pmax.x = fmaxf(pmax.x, v.x); pmax.y = fmaxf(pmax.y, v.y);
            pmax.z = fmaxf(pmax.z, v.z); pmax.w = fmaxf(pmax.w, v.w);
            *(float4*)(ob + t * (2 * HH)) = v;
        }
    }
    spmax[tq][g] = pmax;
    __syncthreads();

    if (tid < 16) {
        float4 a = spmax[0][tid], b2 = spmax[1][tid], c = spmax[2][tid], d = spmax[3][tid];
        float4 m;
        m.x = fmaxf(fmaxf(a.x, b2.x), fmaxf(c.x, d.x));
        m.y = fmaxf(fmaxf(a.y, b2.y), fmaxf(c.y, d.y));
        m.z = fmaxf(fmaxf(a.z, b2.z), fmaxf(c.z, d.z));
        m.w = fmaxf(fmaxf(a.w, b2.w), fmaxf(c.w, d.w));
        smaxf[tid] = m;
    }
    __syncthreads();

    float4 mv = smaxf[g];
    float* obm = ob + HH;
#pragma unroll
    for (int i = 0; i < 9; i++) {
        int t = tq + i * 4;
        if (t < TT) *(float4*)(obm + t * (2 * HH)) = mv;
    }
}

extern "C" void kernel_launch(void* const* d_in, const int* in_sizes, int n_in,
                              void* d_out, int out_size) {
    const float* vox   = (const float*)d_in[0];
    const float* Wm    = (const float*)d_in[1];
    const float* b     = (const float*)d_in[2];
    const float* gamma = (const float*)d_in[3];
    const float* beta  = (const float*)d_in[4];
    float* out = (float*)d_out;

    int N = in_sizes[0] / (TT * CC);

    stats_fold_kernel<<<NB, 256>>>(vox, N, Wm, b, gamma, beta);
    main_kernel<<<N, 64>>>(vox, out);
}

// round 5
// speedup vs baseline: 1.3085x; 1.3085x over previous
#include <cuda_runtime.h>

#define TT 35
#define CC 4
#define CIN 7
#define HH 64
#define BN_EPS 1e-5
#define NB 296          // stats grid size (fixed)
#define NCAP 20480      // per-voxel mean scratch capacity

// per-block partial moments: [stat][block], stat = 28 upper-tri M + 7 S1
__device__ float g_part[35][NB];
__device__ float4 g_mean[NCAP];        // per-voxel mean of ch0..2 (w unused)
__device__ float g_WpT[CIN * HH];      // BN-folded weights, TRANSPOSED [k][j]
__device__ float g_bp[HH];

__device__ __forceinline__ void accum_row(float* acc, float4 r, float mx, float my, float mz) {
    float a[7];
    a[0] = r.x; a[1] = r.y; a[2] = r.z; a[3] = r.w;
    a[4] = r.x - mx; a[5] = r.y - my; a[6] = r.z - mz;
    int idx = 0;
#pragma unroll
    for (int k = 0; k < 7; k++) {
#pragma unroll
        for (int l = 0; l <= k; l++) {
            acc[idx] = fmaf(a[k], a[l], acc[idx]);
            idx++;
        }
    }
#pragma unroll
    for (int k = 0; k < 7; k++) acc[28 + k] += a[k];
}

// Warp-per-voxel moment accumulation. Also writes each voxel's mean to g_mean
// so main_kernel doesn't have to recompute it. Block partials -> g_part
// (plain stores, no global zeroing needed).
__global__ void stats_kernel(const float* __restrict__ vox, int N) {
    const unsigned FULL = 0xffffffffu;
    int lane = threadIdx.x & 31;
    int warpId = (blockIdx.x * blockDim.x + threadIdx.x) >> 5;
    int nWarps = (gridDim.x * blockDim.x) >> 5;

    __shared__ float bacc[35];
    if (threadIdx.x < 35) bacc[threadIdx.x] = 0.f;
    __syncthreads();

    float acc[35];
#pragma unroll
    for (int i = 0; i < 35; i++) acc[i] = 0.f;

    for (int n = warpId; n < N; n += nWarps) {
        const float4* vp = (const float4*)(vox + (size_t)n * (TT * CC));
        float4 r0 = vp[lane];                       // rows 0..31
        float4 r1 = make_float4(0.f, 0.f, 0.f, 0.f);
        bool has2 = (lane < (TT - 32));             // lanes 0..2 take rows 32..34
        if (has2) r1 = vp[lane + 32];

        float sx = r0.x + r1.x;
        float sy = r0.y + r1.y;
        float sz = r0.z + r1.z;
        float rs0 = r0.x + r0.y + r0.z + r0.w;
        float cnt = (rs0 != 0.f) ? 1.f : 0.f;
        if (has2) {
            float rs1 = r1.x + r1.y + r1.z + r1.w;
            if (rs1 != 0.f) cnt += 1.f;
        }
#pragma unroll
        for (int o = 16; o; o >>= 1) {
            sx  += __shfl_down_sync(FULL, sx, o);
            sy  += __shfl_down_sync(FULL, sy, o);
            sz  += __shfl_down_sync(FULL, sz, o);
            cnt += __shfl_down_sync(FULL, cnt, o);
        }
        sx  = __shfl_sync(FULL, sx, 0);
        sy  = __shfl_sync(FULL, sy, 0);
        sz  = __shfl_sync(FULL, sz, 0);
        cnt = __shfl_sync(FULL, cnt, 0);

        float inv = 1.f / cnt;
        float mx = sx * inv, my = sy * inv, mz = sz * inv;

        if (lane == 0 && n < NCAP) g_mean[n] = make_float4(mx, my, mz, 0.f);

        accum_row(acc, r0, mx, my, mz);
        if (has2) accum_row(acc, r1, mx, my, mz);
    }

#pragma unroll
    for (int i = 0; i < 35; i++) {
        float v = acc[i];
#pragma unroll
        for (int o = 16; o; o >>= 1) v += __shfl_down_sync(FULL, v, o);
        if (lane == 0) atomicAdd(&bacc[i], v);
    }
    __syncthreads();
    if (threadIdx.x < 35) g_part[threadIdx.x][blockIdx.x] = bacc[threadIdx.x];
}

// One block: parallel-reduce the per-block partials, then fold BN (batch
// stats from moments) into the linear layer in fp64.
__global__ void fold_kernel(const float* __restrict__ Wm, const float* __restrict__ b,
                            const float* __restrict__ gamma, const float* __restrict__ beta,
                            int N) {
    __shared__ float spart[35][8];
    __shared__ float sstat[35];
    int tid = threadIdx.x;

    if (tid < 280) {
        int s = tid >> 3;        // stat index
        int k = tid & 7;         // sub-summer
        float acc = 0.f;
        for (int bb = k; bb < NB; bb += 8) acc += g_part[s][bb];
        spart[s][k] = acc;
    }
    __syncthreads();
    if (tid < 35) {
        float s = 0.f;
#pragma unroll
        for (int k = 0; k < 8; k++) s += spart[tid][k];
        sstat[tid] = s;
    }
    __syncthreads();

    int j = tid;
    if (j >= HH) return;

    double M[28], S1[7];
#pragma unroll
    for (int i = 0; i < 28; i++) M[i] = (double)sstat[i];
#pragma unroll
    for (int k = 0; k < 7; k++) S1[k] = (double)sstat[28 + k];

    double w[7];
#pragma unroll
    for (int k = 0; k < 7; k++) w[k] = (double)Wm[j * CIN + k];
    double bj = (double)b[j];

    double dotWS = 0.0;
#pragma unroll
    for (int k = 0; k < 7; k++) dotWS += w[k] * S1[k];

    double quad = 0.0;
    int idx = 0;
#pragma unroll
    for (int k = 0; k < 7; k++) {
#pragma unroll
        for (int l = 0; l <= k; l++) {
            double term = w[k] * w[l] * M[idx];
            quad += (l == k) ? term : 2.0 * term;
            idx++;
        }
    }

    double Nt = (double)N * (double)TT;
    double sumx  = dotWS + Nt * bj;
    double sumxx = quad + 2.0 * bj * dotWS + Nt * bj * bj;
    double mu  = sumx / Nt;
    double var = sumxx / Nt - mu * mu;
    double inv = 1.0 / sqrt(var + (double)BN_EPS);
    double a = (double)gamma[j] * inv;

#pragma unroll
    for (int k = 0; k < 7; k++) g_WpT[k * HH + j] = (float)(a * w[k]);
    g_bp[j] = (float)((double)beta[j] + a * (bj - mu));
}

__device__ __forceinline__ void fma4(float4& v, const float4 w, float a) {
    v.x = fmaf(w.x, a, v.x);
    v.y = fmaf(w.y, a, v.y);
    v.z = fmaf(w.z, a, v.z);
    v.w = fmaf(w.w, a, v.w);
}

// 4 voxels per 256-thread block. Sub-group of 64 threads per voxel; thread
// (g = j&15, tq = j>>4) computes channels 4g..4g+3 for rows t ≡ tq (mod 4)
// with BN-folded weights in registers. Means come precomputed from the stats
// kernel, so there is no per-block reduction prologue. All output stores are
// streaming (__stcs) float4.
__global__ __launch_bounds__(256) void main_kernel(const float* __restrict__ vox,
                                                   float* __restrict__ out, int N) {
    __shared__ float4 srow[4 * TT];
    __shared__ float  swpT[CIN][HH];
    __shared__ float  sbp[HH];
    __shared__ float4 spmax[4][4][16];   // [voxel][tq][g]
    __shared__ float4 smaxf[4][16];      // [voxel][g]

    int tid = threadIdx.x;
    int base = blockIdx.x * 4;

    if (tid < HH) {
#pragma unroll
        for (int k = 0; k < CIN; k++) swpT[k][tid] = g_WpT[k * HH + tid];
        sbp[tid] = g_bp[tid];
    }
    // 140 consecutive float4s cover the block's 4 contiguous voxels
    {
        int nv4 = min(4, N - base) * TT;
        if (tid < nv4)
            srow[tid] = ((const float4*)(vox + (size_t)base * (TT * CC)))[tid];
    }
    __syncthreads();

    int sub = tid >> 6;
    int j = tid & 63;
    int g = j & 15, tq = j >> 4;
    int n = base + sub;
    bool active = (n < N);

    float4 pmax = make_float4(0.f, 0.f, 0.f, 0.f);   // ReLU output >= 0
    float* ob = out + (size_t)n * (TT * 2 * HH) + g * 4;

    if (active) {
        float4 w0 = *(const float4*)&swpT[0][g * 4];
        float4 w1 = *(const float4*)&swpT[1][g * 4];
        float4 w2 = *(const float4*)&swpT[2][g * 4];
        float4 w3 = *(const float4*)&swpT[3][g * 4];
        float4 w4 = *(const float4*)&swpT[4][g * 4];
        float4 w5 = *(const float4*)&swpT[5][g * 4];
        float4 w6 = *(const float4*)&swpT[6][g * 4];
        float4 bias = *(const float4*)&sbp[g * 4];

        float mx, my, mz;
        if (n < NCAP) {
            float4 m = g_mean[n];
            mx = m.x; my = m.y; mz = m.z;
        } else {
            // fallback (never hit for this dataset size): recompute serially
            float sx = 0.f, sy = 0.f, sz = 0.f, cnt = 0.f;
            for (int t = 0; t < TT; t++) {
                float4 r = srow[sub * TT + t];
                sx += r.x; sy += r.y; sz += r.z;
                if (r.x + r.y + r.z + r.w != 0.f) cnt += 1.f;
            }
            float inv = 1.f / cnt;
            mx = sx * inv; my = sy * inv; mz = sz * inv;
        }

        const float4* sr = &srow[sub * TT];
#pragma unroll
        for (int i = 0; i < 9; i++) {
            int t = tq + i * 4;
            if (t < TT) {
                float4 r = sr[t];
                float4 v = bias;
                fma4(v, w0, r.x);
                fma4(v, w1, r.y);
                fma4(v, w2, r.z);
                fma4(v, w3, r.w);
                fma4(v, w4, r.x - mx);
                fma4(v, w5, r.y - my);
                fma4(v, w6, r.z - mz);
                v.x = fmaxf(v.x, 0.f); v.y = fmaxf(v.y, 0.f);
                v.z = fmaxf(v.z, 0.f); v.w = fmaxf(v.w, 0.f);
                pmax.x = fmaxf(pmax.x, v.x); pmax.y = fmaxf(pmax.y, v.y);
                pmax.z = fmaxf(pmax.z, v.z); pmax.w = fmaxf(pmax.w, v.w);
                __stcs((float4*)(ob + t * (2 * HH)), v);
            }
        }
    }
    spmax[sub][tq][g] = pmax;
    __syncthreads();

    if (tid < 64) {
        int s2 = tid >> 4, g2 = tid & 15;
        float4 a = spmax[s2][0][g2], b2 = spmax[s2][1][g2];
        float4 c = spmax[s2][2][g2], d = spmax[s2][3][g2];
        float4 m;
        m.x = fmaxf(fmaxf(a.x, b2.x), fmaxf(c.x, d.x));
        m.y = fmaxf(fmaxf(a.y, b2.y), fmaxf(c.y, d.y));
        m.z = fmaxf(fmaxf(a.z, b2.z), fmaxf(c.z, d.z));
        m.w = fmaxf(fmaxf(a.w, b2.w), fmaxf(c.w, d.w));
        smaxf[s2][g2] = m;
    }
    __syncthreads();

    if (active) {
        float4 mv = smaxf[sub][g];
        float* obm = ob + HH;
#pragma unroll
        for (int i = 0; i < 9; i++) {
            int t = tq + i * 4;
            if (t < TT) __stcs((float4*)(obm + t * (2 * HH)), mv);
        }
    }
}

extern "C" void kernel_launch(void* const* d_in, const int* in_sizes, int n_in,
                              void* d_out, int out_size) {
    const float* vox   = (const float*)d_in[0];
    const float* Wm    = (const float*)d_in[1];
    const float* b     = (const float*)d_in[2];
    const float* gamma = (const float*)d_in[3];
    const float* beta  = (const float*)d_in[4];
    float* out = (float*)d_out;

    int N = in_sizes[0] / (TT * CC);

    stats_kernel<<<NB, 256>>>(vox, N);
    fold_kernel<<<1, 288>>>(Wm, b, gamma, beta, N);
    main_kernel<<<(N + 3) / 4, 256>>>(vox, out, N);
}

// round 6
// speedup vs baseline: 1.3446x; 1.0276x over previous
#include <cuda_runtime.h>

#define TT 35
#define CC 4
#define CIN 7
#define HH 64
#define BN_EPS 1e-5
#define NB 592          // stats grid size (fixed)
#define NCAP 20480      // per-voxel mean scratch capacity

// per-block raw partials: stats 0..9 = P (upper-tri of sum v v^T),
// 10..13 = S (sum v), 14..34 = 21 mean-correction accumulators
__device__ float g_part[35][NB];
__device__ float4 g_mean[NCAP];        // per-voxel mean of ch0..2 (w unused)
__device__ float g_WpT[CIN * HH];      // BN-folded weights, TRANSPOSED [k][j]
__device__ float g_bp[HH];

// Mean-free moment accumulation: 8-lane sub-group per voxel, 4 voxels per
// warp. Per row only the pure second moments P and channel sums are
// accumulated (14 FMA, no dependence on the voxel mean); the per-voxel mean
// corrections are O(1) per voxel, computed by each group's sub-lane 0.
__global__ void __launch_bounds__(256, 4) stats_kernel(const float* __restrict__ vox, int N) {
    const unsigned FULL = 0xffffffffu;
    int lane = threadIdx.x & 31;
    int sl = lane & 7;           // sub-lane within 8-lane group
    int grp = lane >> 3;         // group 0..3 -> voxel within quad
    int warpId = (blockIdx.x * blockDim.x + threadIdx.x) >> 5;
    int nWarps = (gridDim.x * blockDim.x) >> 5;
    int nQuads = (N + 3) >> 2;

    __shared__ float bacc[35];
    if (threadIdx.x < 35) bacc[threadIdx.x] = 0.f;
    __syncthreads();

    float accP[10], accS[4], corr[21];
#pragma unroll
    for (int i = 0; i < 10; i++) accP[i] = 0.f;
#pragma unroll
    for (int i = 0; i < 4; i++) accS[i] = 0.f;
#pragma unroll
    for (int i = 0; i < 21; i++) corr[i] = 0.f;

    for (int q = warpId; q < nQuads; q += nWarps) {
        int n = q * 4 + grp;
        bool act = (n < N);
        float s0 = 0.f, s1 = 0.f, s2 = 0.f, s3 = 0.f, cnt = 0.f;

        if (act) {
            const float4* vp = (const float4*)vox + (size_t)n * TT;
#pragma unroll
            for (int i = 0; i < 4; i++) {           // rows sl, sl+8, sl+16, sl+24
                float4 v = vp[sl + 8 * i];
                s0 += v.x; s1 += v.y; s2 += v.z; s3 += v.w;
                float rs = v.x + v.y + v.z + v.w;
                cnt += (rs != 0.f) ? 1.f : 0.f;
                accP[0] = fmaf(v.x, v.x, accP[0]);
                accP[1] = fmaf(v.y, v.x, accP[1]);
                accP[2] = fmaf(v.y, v.y, accP[2]);
                accP[3] = fmaf(v.z, v.x, accP[3]);
                accP[4] = fmaf(v.z, v.y, accP[4]);
                accP[5] = fmaf(v.z, v.z, accP[5]);
                accP[6] = fmaf(v.w, v.x, accP[6]);
                accP[7] = fmaf(v.w, v.y, accP[7]);
                accP[8] = fmaf(v.w, v.z, accP[8]);
                accP[9] = fmaf(v.w, v.w, accP[9]);
            }
            if (sl < TT - 32) {                     // rows 32..34
                float4 v = vp[sl + 32];
                s0 += v.x; s1 += v.y; s2 += v.z; s3 += v.w;
                float rs = v.x + v.y + v.z + v.w;
                cnt += (rs != 0.f) ? 1.f : 0.f;
                accP[0] = fmaf(v.x, v.x, accP[0]);
                accP[1] = fmaf(v.y, v.x, accP[1]);
                accP[2] = fmaf(v.y, v.y, accP[2]);
                accP[3] = fmaf(v.z, v.x, accP[3]);
                accP[4] = fmaf(v.z, v.y, accP[4]);
                accP[5] = fmaf(v.z, v.z, accP[5]);
                accP[6] = fmaf(v.w, v.x, accP[6]);
                accP[7] = fmaf(v.w, v.y, accP[7]);
                accP[8] = fmaf(v.w, v.z, accP[8]);
                accP[9] = fmaf(v.w, v.w, accP[9]);
            }
            // per-lane partial channel sums (pre-reduce, so no overcount)
            accS[0] += s0; accS[1] += s1; accS[2] += s2; accS[3] += s3;
        }

        // 8-lane group reduce of (s0..s3, cnt)
#pragma unroll
        for (int o = 1; o < 8; o <<= 1) {
            s0  += __shfl_xor_sync(FULL, s0, o);
            s1  += __shfl_xor_sync(FULL, s1, o);
            s2  += __shfl_xor_sync(FULL, s2, o);
            s3  += __shfl_xor_sync(FULL, s3, o);
            cnt += __shfl_xor_sync(FULL, cnt, o);
        }

        if (act && sl == 0) {
            float rc = 1.f / cnt;
            float m0 = s0 * rc, m1 = s1 * rc, m2 = s2 * rc;
            if (n < NCAP) g_mean[n] = make_float4(m0, m1, m2, 0.f);
            // cross corrections c = i*4 + l : -m_i * s_l
            corr[0]  -= m0 * s0; corr[1]  -= m0 * s1; corr[2]  -= m0 * s2; corr[3]  -= m0 * s3;
            corr[4]  -= m1 * s0; corr[5]  -= m1 * s1; corr[6]  -= m1 * s2; corr[7]  -= m1 * s3;
            corr[8]  -= m2 * s0; corr[9]  -= m2 * s1; corr[10] -= m2 * s2; corr[11] -= m2 * s3;
            // rel-rel corrections (i>=j): 35 m_i m_j - m_i s_j - m_j s_i
            corr[12] += 35.f * m0 * m0 - 2.f * m0 * s0;
            corr[13] += 35.f * m1 * m0 - m1 * s0 - m0 * s1;
            corr[14] += 35.f * m1 * m1 - 2.f * m1 * s1;
            corr[15] += 35.f * m2 * m0 - m2 * s0 - m0 * s2;
            corr[16] += 35.f * m2 * m1 - m2 * s1 - m1 * s2;
            corr[17] += 35.f * m2 * m2 - 2.f * m2 * s2;
            // S1-rel corrections: -35 m_i
            corr[18] -= 35.f * m0; corr[19] -= 35.f * m1; corr[20] -= 35.f * m2;
        }
    }

    // warp-level reduce: pure over all 32 lanes; corr over the 4 group leaders
#pragma unroll
    for (int o = 16; o; o >>= 1) {
#pragma unroll
        for (int i = 0; i < 10; i++) accP[i] += __shfl_xor_sync(FULL, accP[i], o);
#pragma unroll
        for (int i = 0; i < 4; i++) accS[i] += __shfl_xor_sync(FULL, accS[i], o);
    }
#pragma unroll
    for (int o = 8; o <= 16; o <<= 1) {
#pragma unroll
        for (int c = 0; c < 21; c++) corr[c] += __shfl_xor_sync(FULL, corr[c], o);
    }

    if (lane == 0) {
#pragma unroll
        for (int i = 0; i < 10; i++) atomicAdd(&bacc[i], accP[i]);
#pragma unroll
        for (int i = 0; i < 4; i++) atomicAdd(&bacc[10 + i], accS[i]);
#pragma unroll
        for (int c = 0; c < 21; c++) atomicAdd(&bacc[14 + c], corr[c]);
    }
    __syncthreads();
    if (threadIdx.x < 35) g_part[threadIdx.x][blockIdx.x] = bacc[threadIdx.x];
}

// One block: parallel-reduce partials, map raw pure+corr stats to M/S1 in
// fp64, then fold BN (batch stats from moments) into the linear layer.
__global__ void fold_kernel(const float* __restrict__ Wm, const float* __restrict__ b,
                            const float* __restrict__ gamma, const float* __restrict__ beta,
                            int N) {
    __shared__ float spart[35][8];
    __shared__ double sstat[35];     // assembled M(0..27), S1(28..34)
    __shared__ double sraw[35];
    int tid = threadIdx.x;

    if (tid < 280) {
        int s = tid >> 3;
        int k = tid & 7;
        float acc = 0.f;
        for (int bb = k; bb < NB; bb += 8) acc += g_part[s][bb];
        spart[s][k] = acc;
    }
    __syncthreads();
    if (tid < 35) {
        double s = 0.0;
#pragma unroll
        for (int k = 0; k < 8; k++) s += (double)spart[tid][k];
        sraw[tid] = s;
    }
    __syncthreads();

    if (tid < 35) {
        // raw layout: 0..9 P, 10..13 S, 14..34 corr
        static const int pureTab[35] = {0,1,2,3,4,5,6,7,8,9,
                                        0,1,3,6, 0, 1,2,4,7, 1,2, 3,4,5,8, 3,4,5,
                                        10,11,12,13, 10,11,12};
        static const int corrTab[35] = {-1,-1,-1,-1,-1,-1,-1,-1,-1,-1,
                                        0,1,2,3, 12, 4,5,6,7, 13,14, 8,9,10,11, 15,16,17,
                                        -1,-1,-1,-1, 18,19,20};
        double v = sraw[pureTab[tid]];
        int c = corrTab[tid];
        if (c >= 0) v += sraw[14 + c];
        sstat[tid] = v;
    }
    __syncthreads();

    int j = tid;
    if (j >= HH) return;

    double M[28], S1[7];
#pragma unroll
    for (int i = 0; i < 28; i++) M[i] = sstat[i];
#pragma unroll
    for (int k = 0; k < 7; k++) S1[k] = sstat[28 + k];

    double w[7];
#pragma unroll
    for (int k = 0; k < 7; k++) w[k] = (double)Wm[j * CIN + k];
    double bj = (double)b[j];

    double dotWS = 0.0;
#pragma unroll
    for (int k = 0; k < 7; k++) dotWS += w[k] * S1[k];

    double quad = 0.0;
    int idx = 0;
#pragma unroll
    for (int k = 0; k < 7; k++) {
#pragma unroll
        for (int l = 0; l <= k; l++) {
            double term = w[k] * w[l] * M[idx];
            quad += (l == k) ? term : 2.0 * term;
            idx++;
        }
    }

    double Nt = (double)N * (double)TT;
    double sumx  = dotWS + Nt * bj;
    double sumxx = quad + 2.0 * bj * dotWS + Nt * bj * bj;
    double mu  = sumx / Nt;
    double var = sumxx / Nt - mu * mu;
    double inv = 1.0 / sqrt(var + (double)BN_EPS);
    double a = (double)gamma[j] * inv;

#pragma unroll
    for (int k = 0; k < 7; k++) g_WpT[k * HH + j] = (float)(a * w[k]);
    g_bp[j] = (float)((double)beta[j] + a * (bj - mu));
}

__device__ __forceinline__ void fma4(float4& v, const float4 w, float a) {
    v.x = fmaf(w.x, a, v.x);
    v.y = fmaf(w.y, a, v.y);
    v.z = fmaf(w.z, a, v.z);
    v.w = fmaf(w.w, a, v.w);
}

// 4 voxels per 256-thread block. Sub-group of 64 threads per voxel; thread
// (g = j&15, tq = j>>4) computes channels 4g..4g+3 for rows t ≡ tq (mod 4)
// with BN-folded weights in registers. Means come precomputed from the stats
// kernel. All output stores are streaming (__stcs) float4.
__global__ __launch_bounds__(256) void main_kernel(const float* __restrict__ vox,
                                                   float* __restrict__ out, int N) {
    __shared__ float4 srow[4 * TT];
    __shared__ float  swpT[CIN][HH];
    __shared__ float  sbp[HH];
    __shared__ float4 spmax[4][4][16];   // [voxel][tq][g]
    __shared__ float4 smaxf[4][16];      // [voxel][g]

    int tid = threadIdx.x;
    int base = blockIdx.x * 4;

    if (tid < HH) {
#pragma unroll
        for (int k = 0; k < CIN; k++) swpT[k][tid] = g_WpT[k * HH + tid];
        sbp[tid] = g_bp[tid];
    }
    {
        int nv4 = min(4, N - base) * TT;
        if (tid < nv4)
            srow[tid] = ((const float4*)(vox + (size_t)base * (TT * CC)))[tid];
    }
    __syncthreads();

    int sub = tid >> 6;
    int j = tid & 63;
    int g = j & 15, tq = j >> 4;
    int n = base + sub;
    bool active = (n < N);

    float4 pmax = make_float4(0.f, 0.f, 0.f, 0.f);   // ReLU output >= 0
    float* ob = out + (size_t)n * (TT * 2 * HH) + g * 4;

    if (active) {
        float4 w0 = *(const float4*)&swpT[0][g * 4];
        float4 w1 = *(const float4*)&swpT[1][g * 4];
        float4 w2 = *(const float4*)&swpT[2][g * 4];
        float4 w3 = *(const float4*)&swpT[3][g * 4];
        float4 w4 = *(const float4*)&swpT[4][g * 4];
        float4 w5 = *(const float4*)&swpT[5][g * 4];
        float4 w6 = *(const float4*)&swpT[6][g * 4];
        float4 bias = *(const float4*)&sbp[g * 4];

        float mx, my, mz;
        if (n < NCAP) {
            float4 m = g_mean[n];
            mx = m.x; my = m.y; mz = m.z;
        } else {
            float sx = 0.f, sy = 0.f, sz = 0.f, cnt = 0.f;
            for (int t = 0; t < TT; t++) {
                float4 r = srow[sub * TT + t];
                sx += r.x; sy += r.y; sz += r.z;
                if (r.x + r.y + r.z + r.w != 0.f) cnt += 1.f;
            }
            float inv = 1.f / cnt;
            mx = sx * inv; my = sy * inv; mz = sz * inv;
        }

        const float4* sr = &srow[sub * TT];
#pragma unroll
        for (int i = 0; i < 9; i++) {
            int t = tq + i * 4;
            if (t < TT) {
                float4 r = sr[t];
                float4 v = bias;
                fma4(v, w0, r.x);
                fma4(v, w1, r.y);
                fma4(v, w2, r.z);
                fma4(v, w3, r.w);
                fma4(v, w4, r.x - mx);
                fma4(v, w5, r.y - my);
                fma4(v, w6, r.z - mz);
                v.x = fmaxf(v.x, 0.f); v.y = fmaxf(v.y, 0.f);
                v.z = fmaxf(v.z, 0.f); v.w = fmaxf(v.w, 0.f);
                pmax.x = fmaxf(pmax.x, v.x); pmax.y = fmaxf(pmax.y, v.y);
                pmax.z = fmaxf(pmax.z, v.z); pmax.w = fmaxf(pmax.w, v.w);
                __stcs((float4*)(ob + t * (2 * HH)), v);
            }
        }
    }
    spmax[sub][tq][g] = pmax;
    __syncthreads();

    if (tid < 64) {
        int s2 = tid >> 4, g2 = tid & 15;
        float4 a = spmax[s2][0][g2], b2 = spmax[s2][1][g2];
        float4 c = spmax[s2][2][g2], d = spmax[s2][3][g2];
        float4 m;
        m.x = fmaxf(fmaxf(a.x, b2.x), fmaxf(c.x, d.x));
        m.y = fmaxf(fmaxf(a.y, b2.y), fmaxf(c.y, d.y));
        m.z = fmaxf(fmaxf(a.z, b2.z), fmaxf(c.z, d.z));
        m.w = fmaxf(fmaxf(a.w, b2.w), fmaxf(c.w, d.w));
        smaxf[s2][g2] = m;
    }
    __syncthreads();

    if (active) {
        float4 mv = smaxf[sub][g];
        float* obm = ob + HH;
#pragma unroll
        for (int i = 0; i < 9; i++) {
            int t = tq + i * 4;
            if (t < TT) __stcs((float4*)(obm + t * (2 * HH)), mv);
        }
    }
}

extern "C" void kernel_launch(void* const* d_in, const int* in_sizes, int n_in,
                              void* d_out, int out_size) {
    const float* vox   = (const float*)d_in[0];
    const float* Wm    = (const float*)d_in[1];
    const float* b     = (const float*)d_in[2];
    const float* gamma = (const float*)d_in[3];
    const float* beta  = (const float*)d_in[4];
    float* out = (float*)d_out;

    int N = in_sizes[0] / (TT * CC);

    stats_kernel<<<NB, 256>>>(vox, N);
    fold_kernel<<<1, 288>>>(Wm, b, gamma, beta, N);
    main_kernel<<<(N + 3) / 4, 256>>>(vox, out, N);
}

// round 7
// speedup vs baseline: 1.3848x; 1.0298x over previous
#include <cuda_runtime.h>

#define TT 35
#define CC 4
#define CIN 7
#define HH 64
#define BN_EPS 1e-5
#define NBS 148         // stats grid size: exactly one wave
#define NCAP 20480      // per-voxel mean scratch capacity

// per-block raw partials: stats 0..9 = P (upper-tri of sum v v^T),
// 10..13 = S (sum v), 14..34 = 21 mean-correction accumulators
__device__ float g_part[35][NBS];
__device__ float4 g_mean[NCAP];        // per-voxel mean of ch0..2 (w unused)
__device__ float g_WpT[CIN * HH];      // BN-folded weights, TRANSPOSED [k][j]
__device__ float g_bp[HH];

struct Quad { float4 v[5]; };

__device__ __forceinline__ void load_quad(Quad& qd, const float* __restrict__ vox,
                                          int n, int sl, bool act) {
    if (act) {
        const float4* vp = (const float4*)vox + (size_t)n * TT;
#pragma unroll
        for (int i = 0; i < 4; i++) qd.v[i] = vp[sl + 8 * i];
        qd.v[4] = (sl < TT - 32) ? vp[sl + 32] : make_float4(0.f, 0.f, 0.f, 0.f);
    } else {
#pragma unroll
        for (int i = 0; i < 5; i++) qd.v[i] = make_float4(0.f, 0.f, 0.f, 0.f);
    }
}

// Mean-free moment accumulation, one wave, ~5 quads per warp with explicit
// load prefetch. 8-lane sub-group per voxel, 4 voxels per warp. Inner loop:
// 14 FMA/row pure moments (no mean dependence); per-voxel corrections are
// O(1), computed by each group's sub-lane 0 from the 8-lane (s,cnt) reduce.
__global__ void __launch_bounds__(256) stats_kernel(const float* __restrict__ vox, int N) {
    const unsigned FULL = 0xffffffffu;
    int lane = threadIdx.x & 31;
    int sl = lane & 7;           // sub-lane within 8-lane group
    int grp = lane >> 3;         // group 0..3 -> voxel within quad
    int wInB = threadIdx.x >> 5;
    int gwarp = blockIdx.x * 8 + wInB;
    const int warpsTotal = NBS * 8;

    int nQuads = (N + 3) >> 2;
    int per = (nQuads + warpsTotal - 1) / warpsTotal;
    int q0 = gwarp * per;
    int q1 = min(q0 + per, nQuads);

    __shared__ float swacc[8][35];

    float accP[10], accS[4], corr[21];
#pragma unroll
    for (int i = 0; i < 10; i++) accP[i] = 0.f;
#pragma unroll
    for (int i = 0; i < 4; i++) accS[i] = 0.f;
#pragma unroll
    for (int i = 0; i < 21; i++) corr[i] = 0.f;

    Quad cur, nxt;
    if (q0 < q1) {
        int n = q0 * 4 + grp;
        load_quad(cur, vox, n, sl, n < N);
    }

    for (int q = q0; q < q1; q++) {
        // prefetch next quad while this one computes
        if (q + 1 < q1) {
            int nn = (q + 1) * 4 + grp;
            load_quad(nxt, vox, nn, sl, nn < N);
        }

        int n = q * 4 + grp;
        bool act = (n < N);

        float s0 = 0.f, s1 = 0.f, s2 = 0.f, s3 = 0.f, cnt = 0.f;
#pragma unroll
        for (int i = 0; i < 5; i++) {
            float4 v = cur.v[i];
            s0 += v.x; s1 += v.y; s2 += v.z; s3 += v.w;
            float rs = v.x + v.y + v.z + v.w;
            cnt += (rs != 0.f) ? 1.f : 0.f;
            accP[0] = fmaf(v.x, v.x, accP[0]);
            accP[1] = fmaf(v.y, v.x, accP[1]);
            accP[2] = fmaf(v.y, v.y, accP[2]);
            accP[3] = fmaf(v.z, v.x, accP[3]);
            accP[4] = fmaf(v.z, v.y, accP[4]);
            accP[5] = fmaf(v.z, v.z, accP[5]);
            accP[6] = fmaf(v.w, v.x, accP[6]);
            accP[7] = fmaf(v.w, v.y, accP[7]);
            accP[8] = fmaf(v.w, v.z, accP[8]);
            accP[9] = fmaf(v.w, v.w, accP[9]);
        }
        accS[0] += s0; accS[1] += s1; accS[2] += s2; accS[3] += s3;

        // 8-lane group reduce of (s0..s3, cnt)
#pragma unroll
        for (int o = 1; o < 8; o <<= 1) {
            s0  += __shfl_xor_sync(FULL, s0, o);
            s1  += __shfl_xor_sync(FULL, s1, o);
            s2  += __shfl_xor_sync(FULL, s2, o);
            s3  += __shfl_xor_sync(FULL, s3, o);
            cnt += __shfl_xor_sync(FULL, cnt, o);
        }

        if (act && sl == 0) {
            float rc = 1.f / cnt;
            float m0 = s0 * rc, m1 = s1 * rc, m2 = s2 * rc;
            if (n < NCAP) g_mean[n] = make_float4(m0, m1, m2, 0.f);
            // cross corrections c = i*4 + l : -m_i * s_l
            corr[0]  -= m0 * s0; corr[1]  -= m0 * s1; corr[2]  -= m0 * s2; corr[3]  -= m0 * s3;
            corr[4]  -= m1 * s0; corr[5]  -= m1 * s1; corr[6]  -= m1 * s2; corr[7]  -= m1 * s3;
            corr[8]  -= m2 * s0; corr[9]  -= m2 * s1; corr[10] -= m2 * s2; corr[11] -= m2 * s3;
            // rel-rel corrections (i>=j): 35 m_i m_j - m_i s_j - m_j s_i
            corr[12] += 35.f * m0 * m0 - 2.f * m0 * s0;
            corr[13] += 35.f * m1 * m0 - m1 * s0 - m0 * s1;
            corr[14] += 35.f * m1 * m1 - 2.f * m1 * s1;
            corr[15] += 35.f * m2 * m0 - m2 * s0 - m0 * s2;
            corr[16] += 35.f * m2 * m1 - m2 * s1 - m1 * s2;
            corr[17] += 35.f * m2 * m2 - 2.f * m2 * s2;
            // S1-rel corrections: -35 m_i
            corr[18] -= 35.f * m0; corr[19] -= 35.f * m1; corr[20] -= 35.f * m2;
        }

        cur = nxt;
    }

    // warp-level reduce: pure over all 32 lanes; corr over the 4 group leaders
#pragma unroll
    for (int o = 16; o; o >>= 1) {
#pragma unroll
        for (int i = 0; i < 10; i++) accP[i] += __shfl_xor_sync(FULL, accP[i], o);
#pragma unroll
        for (int i = 0; i < 4; i++) accS[i] += __shfl_xor_sync(FULL, accS[i], o);
    }
#pragma unroll
    for (int o = 8; o <= 16; o <<= 1) {
#pragma unroll
        for (int c = 0; c < 21; c++) corr[c] += __shfl_xor_sync(FULL, corr[c], o);
    }

    if (lane == 0) {
#pragma unroll
        for (int i = 0; i < 10; i++) swacc[wInB][i] = accP[i];
#pragma unroll
        for (int i = 0; i < 4; i++) swacc[wInB][10 + i] = accS[i];
#pragma unroll
        for (int c = 0; c < 21; c++) swacc[wInB][14 + c] = corr[c];
    }
    __syncthreads();
    if (threadIdx.x < 35) {
        float s = 0.f;
#pragma unroll
        for (int w = 0; w < 8; w++) s += swacc[w][threadIdx.x];
        g_part[threadIdx.x][blockIdx.x] = s;
    }
}

// One block: parallel-reduce partials, map raw pure+corr stats to M/S1 in
// fp64, then fold BN (batch stats from moments) into the linear layer.
__global__ void fold_kernel(const float* __restrict__ Wm, const float* __restrict__ b,
                            const float* __restrict__ gamma, const float* __restrict__ beta,
                            int N) {
    __shared__ float spart[35][8];
    __shared__ double sstat[35];     // assembled M(0..27), S1(28..34)
    __shared__ double sraw[35];
    int tid = threadIdx.x;

    if (tid < 280) {
        int s = tid >> 3;
        int k = tid & 7;
        float acc = 0.f;
        for (int bb = k; bb < NBS; bb += 8) acc += g_part[s][bb];
        spart[s][k] = acc;
    }
    __syncthreads();
    if (tid < 35) {
        double s = 0.0;
#pragma unroll
        for (int k = 0; k < 8; k++) s += (double)spart[tid][k];
        sraw[tid] = s;
    }
    __syncthreads();

    if (tid < 35) {
        // raw layout: 0..9 P, 10..13 S, 14..34 corr
        static const int pureTab[35] = {0,1,2,3,4,5,6,7,8,9,
                                        0,1,3,6, 0, 1,2,4,7, 1,2, 3,4,5,8, 3,4,5,
                                        10,11,12,13, 10,11,12};
        static const int corrTab[35] = {-1,-1,-1,-1,-1,-1,-1,-1,-1,-1,
                                        0,1,2,3, 12, 4,5,6,7, 13,14, 8,9,10,11, 15,16,17,
                                        -1,-1,-1,-1, 18,19,20};
        double v = sraw[pureTab[tid]];
        int c = corrTab[tid];
        if (c >= 0) v += sraw[14 + c];
        sstat[tid] = v;
    }
    __syncthreads();

    int j = tid;
    if (j >= HH) return;

    double M[28], S1[7];
#pragma unroll
    for (int i = 0; i < 28; i++) M[i] = sstat[i];
#pragma unroll
    for (int k = 0; k < 7; k++) S1[k] = sstat[28 + k];

    double w[7];
#pragma unroll
    for (int k = 0; k < 7; k++) w[k] = (double)Wm[j * CIN + k];
    double bj = (double)b[j];

    double dotWS = 0.0;
#pragma unroll
    for (int k = 0; k < 7; k++) dotWS += w[k] * S1[k];

    double quad = 0.0;
    int idx = 0;
#pragma unroll
    for (int k = 0; k < 7; k++) {
#pragma unroll
        for (int l = 0; l <= k; l++) {
            double term = w[k] * w[l] * M[idx];
            quad += (l == k) ? term : 2.0 * term;
            idx++;
        }
    }

    double Nt = (double)N * (double)TT;
    double sumx  = dotWS + Nt * bj;
    double sumxx = quad + 2.0 * bj * dotWS + Nt * bj * bj;
    double mu  = sumx / Nt;
    double var = sumxx / Nt - mu * mu;
    double inv = 1.0 / sqrt(var + (double)BN_EPS);
    double a = (double)gamma[j] * inv;

#pragma unroll
    for (int k = 0; k < 7; k++) g_WpT[k * HH + j] = (float)(a * w[k]);
    g_bp[j] = (float)((double)beta[j] + a * (bj - mu));
}

__device__ __forceinline__ void fma4(float4& v, const float4 w, float a) {
    v.x = fmaf(w.x, a, v.x);
    v.y = fmaf(w.y, a, v.y);
    v.z = fmaf(w.z, a, v.z);
    v.w = fmaf(w.w, a, v.w);
}

// 4 voxels per 256-thread block. Sub-group of 64 threads per voxel; thread
// (g = j&15, tq = j>>4) computes channels 4g..4g+3 for rows t ≡ tq (mod 4)
// with BN-folded weights in registers. Means come precomputed from the stats
// kernel. All output stores are streaming (__stcs) float4.
__global__ __launch_bounds__(256) void main_kernel(const float* __restrict__ vox,
                                                   float* __restrict__ out, int N) {
    __shared__ float4 srow[4 * TT];
    __shared__ float  swpT[CIN][HH];
    __shared__ float  sbp[HH];
    __shared__ float4 spmax[4][4][16];   // [voxel][tq][g]
    __shared__ float4 smaxf[4][16];      // [voxel][g]

    int tid = threadIdx.x;
    int base = blockIdx.x * 4;

    if (tid < HH) {
#pragma unroll
        for (int k = 0; k < CIN; k++) swpT[k][tid] = g_WpT[k * HH + tid];
        sbp[tid] = g_bp[tid];
    }
    {
        int nv4 = min(4, N - base) * TT;
        if (tid < nv4)
            srow[tid] = ((const float4*)(vox + (size_t)base * (TT * CC)))[tid];
    }
    __syncthreads();

    int sub = tid >> 6;
    int j = tid & 63;
    int g = j & 15, tq = j >> 4;
    int n = base + sub;
    bool active = (n < N);

    float4 pmax = make_float4(0.f, 0.f, 0.f, 0.f);   // ReLU output >= 0
    float* ob = out + (size_t)n * (TT * 2 * HH) + g * 4;

    if (active) {
        float4 w0 = *(const float4*)&swpT[0][g * 4];
        float4 w1 = *(const float4*)&swpT[1][g * 4];
        float4 w2 = *(const float4*)&swpT[2][g * 4];
        float4 w3 = *(const float4*)&swpT[3][g * 4];
        float4 w4 = *(const float4*)&swpT[4][g * 4];
        float4 w5 = *(const float4*)&swpT[5][g * 4];
        float4 w6 = *(const float4*)&swpT[6][g * 4];
        float4 bias = *(const float4*)&sbp[g * 4];

        float mx, my, mz;
        if (n < NCAP) {
            float4 m = g_mean[n];
            mx = m.x; my = m.y; mz = m.z;
        } else {
            float sx = 0.f, sy = 0.f, sz = 0.f, cnt = 0.f;
            for (int t = 0; t < TT; t++) {
                float4 r = srow[sub * TT + t];
                sx += r.x; sy += r.y; sz += r.z;
                if (r.x + r.y + r.z + r.w != 0.f) cnt += 1.f;
            }
            float inv = 1.f / cnt;
            mx = sx * inv; my = sy * inv; mz = sz * inv;
        }

        const float4* sr = &srow[sub * TT];
#pragma unroll
        for (int i = 0; i < 9; i++) {
            int t = tq + i * 4;
            if (t < TT) {
                float4 r = sr[t];
                float4 v = bias;
                fma4(v, w0, r.x);
                fma4(v, w1, r.y);
                fma4(v, w2, r.z);
                fma4(v, w3, r.w);
                fma4(v, w4, r.x - mx);
                fma4(v, w5, r.y - my);
                fma4(v, w6, r.z - mz);
                v.x = fmaxf(v.x, 0.f); v.y = fmaxf(v.y, 0.f);
                v.z = fmaxf(v.z, 0.f); v.w = fmaxf(v.w, 0.f);
                pmax.x = fmaxf(pmax.x, v.x); pmax.y = fmaxf(pmax.y, v.y);
                pmax.z = fmaxf(pmax.z, v.z); pmax.w = fmaxf(pmax.w, v.w);
                __stcs((float4*)(ob + t * (2 * HH)), v);
            }
        }
    }
    spmax[sub][tq][g] = pmax;
    __syncthreads();

    if (tid < 64) {
        int s2 = tid >> 4, g2 = tid & 15;
        float4 a = spmax[s2][0][g2], b2 = spmax[s2][1][g2];
        float4 c = spmax[s2][2][g2], d = spmax[s2][3][g2];
        float4 m;
        m.x = fmaxf(fmaxf(a.x, b2.x), fmaxf(c.x, d.x));
        m.y = fmaxf(fmaxf(a.y, b2.y), fmaxf(c.y, d.y));
        m.z = fmaxf(fmaxf(a.z, b2.z), fmaxf(c.z, d.z));
        m.w = fmaxf(fmaxf(a.w, b2.w), fmaxf(c.w, d.w));
        smaxf[s2][g2] = m;
    }
    __syncthreads();

    if (active) {
        float4 mv = smaxf[sub][g];
        float* obm = ob + HH;
#pragma unroll
        for (int i = 0; i < 9; i++) {
            int t = tq + i * 4;
            if (t < TT) __stcs((float4*)(obm + t * (2 * HH)), mv);
        }
    }
}

extern "C" void kernel_launch(void* const* d_in, const int* in_sizes, int n_in,
                              void* d_out, int out_size) {
    const float* vox   = (const float*)d_in[0];
    const float* Wm    = (const float*)d_in[1];
    const float* b     = (const float*)d_in[2];
    const float* gamma = (const float*)d_in[3];
    const float* beta  = (const float*)d_in[4];
    float* out = (float*)d_out;

    int N = in_sizes[0] / (TT * CC);

    stats_kernel<<<NBS, 256>>>(vox, N);
    fold_kernel<<<1, 288>>>(Wm, b, gamma, beta, N);
    main_kernel<<<(N + 3) / 4, 256>>>(vox, out, N);
}

// round 8
// speedup vs baseline: 1.4619x; 1.0557x over previous
#include <cuda_runtime.h>

#define TT 35
#define CC 4
#define CIN 7
#define HH 64
#define BN_EPS 1e-5
#define NBS 296         // stats grid size: 2 blocks/SM, one wave
#define NCAP 20480      // per-voxel mean scratch capacity

// per-block raw partials: stats 0..9 = P (upper-tri of sum v v^T),
// 10..13 = S (sum v), 14..34 = 21 mean-correction accumulators
__device__ float g_part[35][NBS];
__device__ float4 g_mean[NCAP];        // per-voxel mean of ch0..2 (w unused)
__device__ float g_WpT[CIN * HH];      // BN-folded weights, TRANSPOSED [k][j]
__device__ float g_bp[HH];

struct Quad { float4 v[5]; };

__device__ __forceinline__ void load_quad(Quad& qd, const float* __restrict__ vox,
                                          int n, int sl, bool act) {
    if (act) {
        const float4* vp = (const float4*)vox + (size_t)n * TT;
#pragma unroll
        for (int i = 0; i < 4; i++) qd.v[i] = vp[sl + 8 * i];
        qd.v[4] = (sl < TT - 32) ? vp[sl + 32] : make_float4(0.f, 0.f, 0.f, 0.f);
    } else {
#pragma unroll
        for (int i = 0; i < 5; i++) qd.v[i] = make_float4(0.f, 0.f, 0.f, 0.f);
    }
}

// Mean-free moment accumulation, one wave at 2 blocks/SM, 2-3 quads per warp
// (balanced contiguous split) with explicit load prefetch. 8-lane sub-group
// per voxel, 4 voxels per warp. Inner loop: 14 FMA/row pure moments (no
// dependence on the voxel mean); per-voxel corrections are O(1), computed by
// each group's sub-lane 0 from the 8-lane (s,cnt) reduce.
__global__ void __launch_bounds__(256) stats_kernel(const float* __restrict__ vox, int N) {
    const unsigned FULL = 0xffffffffu;
    int lane = threadIdx.x & 31;
    int sl = lane & 7;           // sub-lane within 8-lane group
    int grp = lane >> 3;         // group 0..3 -> voxel within quad
    int wInB = threadIdx.x >> 5;
    int gwarp = blockIdx.x * 8 + wInB;
    const int warpsTotal = NBS * 8;

    int nQuads = (N + 3) >> 2;
    int q0 = (int)(((long long)gwarp * nQuads) / warpsTotal);
    int q1 = (int)(((long long)(gwarp + 1) * nQuads) / warpsTotal);

    __shared__ float swacc[8][35];

    float accP[10], accS[4], corr[21];
#pragma unroll
    for (int i = 0; i < 10; i++) accP[i] = 0.f;
#pragma unroll
    for (int i = 0; i < 4; i++) accS[i] = 0.f;
#pragma unroll
    for (int i = 0; i < 21; i++) corr[i] = 0.f;

    Quad cur, nxt;
    if (q0 < q1) {
        int n = q0 * 4 + grp;
        load_quad(cur, vox, n, sl, n < N);
    }

    for (int q = q0; q < q1; q++) {
        // prefetch next quad while this one computes
        if (q + 1 < q1) {
            int nn = (q + 1) * 4 + grp;
            load_quad(nxt, vox, nn, sl, nn < N);
        }

        int n = q * 4 + grp;
        bool act = (n < N);

        float s0 = 0.f, s1 = 0.f, s2 = 0.f, s3 = 0.f, cnt = 0.f;
#pragma unroll
        for (int i = 0; i < 5; i++) {
            float4 v = cur.v[i];
            s0 += v.x; s1 += v.y; s2 += v.z; s3 += v.w;
            float rs = v.x + v.y + v.z + v.w;
            cnt += (rs != 0.f) ? 1.f : 0.f;
            accP[0] = fmaf(v.x, v.x, accP[0]);
            accP[1] = fmaf(v.y, v.x, accP[1]);
            accP[2] = fmaf(v.y, v.y, accP[2]);
            accP[3] = fmaf(v.z, v.x, accP[3]);
            accP[4] = fmaf(v.z, v.y, accP[4]);
            accP[5] = fmaf(v.z, v.z, accP[5]);
            accP[6] = fmaf(v.w, v.x, accP[6]);
            accP[7] = fmaf(v.w, v.y, accP[7]);
            accP[8] = fmaf(v.w, v.z, accP[8]);
            accP[9] = fmaf(v.w, v.w, accP[9]);
        }
        accS[0] += s0; accS[1] += s1; accS[2] += s2; accS[3] += s3;

        // 8-lane group reduce of (s0..s3, cnt)
#pragma unroll
        for (int o = 1; o < 8; o <<= 1) {
            s0  += __shfl_xor_sync(FULL, s0, o);
            s1  += __shfl_xor_sync(FULL, s1, o);
            s2  += __shfl_xor_sync(FULL, s2, o);
            s3  += __shfl_xor_sync(FULL, s3, o);
            cnt += __shfl_xor_sync(FULL, cnt, o);
        }

        if (act && sl == 0) {
            float rc = 1.f / cnt;
            float m0 = s0 * rc, m1 = s1 * rc, m2 = s2 * rc;
            if (n < NCAP) g_mean[n] = make_float4(m0, m1, m2, 0.f);
            // cross corrections c = i*4 + l : -m_i * s_l
            corr[0]  -= m0 * s0; corr[1]  -= m0 * s1; corr[2]  -= m0 * s2; corr[3]  -= m0 * s3;
            corr[4]  -= m1 * s0; corr[5]  -= m1 * s1; corr[6]  -= m1 * s2; corr[7]  -= m1 * s3;
            corr[8]  -= m2 * s0; corr[9]  -= m2 * s1; corr[10] -= m2 * s2; corr[11] -= m2 * s3;
            // rel-rel corrections (i>=j): 35 m_i m_j - m_i s_j - m_j s_i
            corr[12] += 35.f * m0 * m0 - 2.f * m0 * s0;
            corr[13] += 35.f * m1 * m0 - m1 * s0 - m0 * s1;
            corr[14] += 35.f * m1 * m1 - 2.f * m1 * s1;
            corr[15] += 35.f * m2 * m0 - m2 * s0 - m0 * s2;
            corr[16] += 35.f * m2 * m1 - m2 * s1 - m1 * s2;
            corr[17] += 35.f * m2 * m2 - 2.f * m2 * s2;
            // S1-rel corrections: -35 m_i
            corr[18] -= 35.f * m0; corr[19] -= 35.f * m1; corr[20] -= 35.f * m2;
        }

        cur = nxt;
    }

    // warp-level reduce: pure over all 32 lanes; corr over the 4 group leaders
#pragma unroll
    for (int o = 16; o; o >>= 1) {
#pragma unroll
        for (int i = 0; i < 10; i++) accP[i] += __shfl_xor_sync(FULL, accP[i], o);
#pragma unroll
        for (int i = 0; i < 4; i++) accS[i] += __shfl_xor_sync(FULL, accS[i], o);
    }
#pragma unroll
    for (int o = 8; o <= 16; o <<= 1) {
#pragma unroll
        for (int c = 0; c < 21; c++) corr[c] += __shfl_xor_sync(FULL, corr[c], o);
    }

    if (lane == 0) {
#pragma unroll
        for (int i = 0; i < 10; i++) swacc[wInB][i] = accP[i];
#pragma unroll
        for (int i = 0; i < 4; i++) swacc[wInB][10 + i] = accS[i];
#pragma unroll
        for (int c = 0; c < 21; c++) swacc[wInB][14 + c] = corr[c];
    }
    __syncthreads();
    if (threadIdx.x < 35) {
        float s = 0.f;
#pragma unroll
        for (int w = 0; w < 8; w++) s += swacc[w][threadIdx.x];
        g_part[threadIdx.x][blockIdx.x] = s;
    }
}

// One block: parallel-reduce partials, map raw pure+corr stats to M/S1 in
// fp64, then fold BN (batch stats from moments) into the linear layer.
__global__ void fold_kernel(const float* __restrict__ Wm, const float* __restrict__ b,
                            const float* __restrict__ gamma, const float* __restrict__ beta,
                            int N) {
    __shared__ float spart[35][8];
    __shared__ double sstat[35];     // assembled M(0..27), S1(28..34)
    __shared__ double sraw[35];
    int tid = threadIdx.x;

    if (tid < 280) {
        int s = tid >> 3;
        int k = tid & 7;
        float acc = 0.f;
        for (int bb = k; bb < NBS; bb += 8) acc += g_part[s][bb];
        spart[s][k] = acc;
    }
    __syncthreads();
    if (tid < 35) {
        double s = 0.0;
#pragma unroll
        for (int k = 0; k < 8; k++) s += (double)spart[tid][k];
        sraw[tid] = s;
    }
    __syncthreads();

    if (tid < 35) {
        // raw layout: 0..9 P, 10..13 S, 14..34 corr
        static const int pureTab[35] = {0,1,2,3,4,5,6,7,8,9,
                                        0,1,3,6, 0, 1,2,4,7, 1,2, 3,4,5,8, 3,4,5,
                                        10,11,12,13, 10,11,12};
        static const int corrTab[35] = {-1,-1,-1,-1,-1,-1,-1,-1,-1,-1,
                                        0,1,2,3, 12, 4,5,6,7, 13,14, 8,9,10,11, 15,16,17,
                                        -1,-1,-1,-1, 18,19,20};
        double v = sraw[pureTab[tid]];
        int c = corrTab[tid];
        if (c >= 0) v += sraw[14 + c];
        sstat[tid] = v;
    }
    __syncthreads();

    int j = tid;
    if (j >= HH) return;

    double M[28], S1[7];
#pragma unroll
    for (int i = 0; i < 28; i++) M[i] = sstat[i];
#pragma unroll
    for (int k = 0; k < 7; k++) S1[k] = sstat[28 + k];

    double w[7];
#pragma unroll
    for (int k = 0; k < 7; k++) w[k] = (double)Wm[j * CIN + k];
    double bj = (double)b[j];

    double dotWS = 0.0;
#pragma unroll
    for (int k = 0; k < 7; k++) dotWS += w[k] * S1[k];

    double quad = 0.0;
    int idx = 0;
#pragma unroll
    for (int k = 0; k < 7; k++) {
#pragma unroll
        for (int l = 0; l <= k; l++) {
            double term = w[k] * w[l] * M[idx];
            quad += (l == k) ? term : 2.0 * term;
            idx++;
        }
    }

    double Nt = (double)N * (double)TT;
    double sumx  = dotWS + Nt * bj;
    double sumxx = quad + 2.0 * bj * dotWS + Nt * bj * bj;
    double mu  = sumx / Nt;
    double var = sumxx / Nt - mu * mu;
    double inv = 1.0 / sqrt(var + (double)BN_EPS);
    double a = (double)gamma[j] * inv;

#pragma unroll
    for (int k = 0; k < 7; k++) g_WpT[k * HH + j] = (float)(a * w[k]);
    g_bp[j] = (float)((double)beta[j] + a * (bj - mu));
}

__device__ __forceinline__ void fma4(float4& v, const float4 w, float a) {
    v.x = fmaf(w.x, a, v.x);
    v.y = fmaf(w.y, a, v.y);
    v.z = fmaf(w.z, a, v.z);
    v.w = fmaf(w.w, a, v.w);
}

// 4 voxels per 256-thread block. Sub-group of 64 threads per voxel; thread
// (g = j&15, tq = j>>4) computes channels 4g..4g+3 for rows t ≡ tq (mod 4)
// with BN-folded weights in registers. Means come precomputed from the stats
// kernel. All output stores are streaming (__stcs) float4.
__global__ __launch_bounds__(256) void main_kernel(const float* __restrict__ vox,
                                                   float* __restrict__ out, int N) {
    __shared__ float4 srow[4 * TT];
    __shared__ float  swpT[CIN][HH];
    __shared__ float  sbp[HH];
    __shared__ float4 spmax[4][4][16];   // [voxel][tq][g]
    __shared__ float4 smaxf[4][16];      // [voxel][g]

    int tid = threadIdx.x;
    int base = blockIdx.x * 4;

    if (tid < HH) {
#pragma unroll
        for (int k = 0; k < CIN; k++) swpT[k][tid] = g_WpT[k * HH + tid];
        sbp[tid] = g_bp[tid];
    }
    {
        int nv4 = min(4, N - base) * TT;
        if (tid < nv4)
            srow[tid] = ((const float4*)(vox + (size_t)base * (TT * CC)))[tid];
    }
    __syncthreads();

    int sub = tid >> 6;
    int j = tid & 63;
    int g = j & 15, tq = j >> 4;
    int n = base + sub;
    bool active = (n < N);

    float4 pmax = make_float4(0.f, 0.f, 0.f, 0.f);   // ReLU output >= 0
    float* ob = out + (size_t)n * (TT * 2 * HH) + g * 4;

    if (active) {
        float4 w0 = *(const float4*)&swpT[0][g * 4];
        float4 w1 = *(const float4*)&swpT[1][g * 4];
        float4 w2 = *(const float4*)&swpT[2][g * 4];
        float4 w3 = *(const float4*)&swpT[3][g * 4];
        float4 w4 = *(const float4*)&swpT[4][g * 4];
        float4 w5 = *(const float4*)&swpT[5][g * 4];
        float4 w6 = *(const float4*)&swpT[6][g * 4];
        float4 bias = *(const float4*)&sbp[g * 4];

        float mx, my, mz;
        if (n < NCAP) {
            float4 m = g_mean[n];
            mx = m.x; my = m.y; mz = m.z;
        } else {
            float sx = 0.f, sy = 0.f, sz = 0.f, cnt = 0.f;
            for (int t = 0; t < TT; t++) {
                float4 r = srow[sub * TT + t];
                sx += r.x; sy += r.y; sz += r.z;
                if (r.x + r.y + r.z + r.w != 0.f) cnt += 1.f;
            }
            float inv = 1.f / cnt;
            mx = sx * inv; my = sy * inv; mz = sz * inv;
        }

        const float4* sr = &srow[sub * TT];
#pragma unroll
        for (int i = 0; i < 9; i++) {
            int t = tq + i * 4;
            if (t < TT) {
                float4 r = sr[t];
                float4 v = bias;
                fma4(v, w0, r.x);
                fma4(v, w1, r.y);
                fma4(v, w2, r.z);
                fma4(v, w3, r.w);
                fma4(v, w4, r.x - mx);
                fma4(v, w5, r.y - my);
                fma4(v, w6, r.z - mz);
                v.x = fmaxf(v.x, 0.f); v.y = fmaxf(v.y, 0.f);
                v.z = fmaxf(v.z, 0.f); v.w = fmaxf(v.w, 0.f);
                pmax.x = fmaxf(pmax.x, v.x); pmax.y = fmaxf(pmax.y, v.y);
                pmax.z = fmaxf(pmax.z, v.z); pmax.w = fmaxf(pmax.w, v.w);
                __stcs((float4*)(ob + t * (2 * HH)), v);
            }
        }
    }
    spmax[sub][tq][g] = pmax;
    __syncthreads();

    if (tid < 64) {
        int s2 = tid >> 4, g2 = tid & 15;
        float4 a = spmax[s2][0][g2], b2 = spmax[s2][1][g2];
        float4 c = spmax[s2][2][g2], d = spmax[s2][3][g2];
        float4 m;
        m.x = fmaxf(fmaxf(a.x, b2.x), fmaxf(c.x, d.x));
        m.y = fmaxf(fmaxf(a.y, b2.y), fmaxf(c.y, d.y));
        m.z = fmaxf(fmaxf(a.z, b2.z), fmaxf(c.z, d.z));
        m.w = fmaxf(fmaxf(a.w, b2.w), fmaxf(c.w, d.w));
        smaxf[s2][g2] = m;
    }
    __syncthreads();

    if (active) {
        float4 mv = smaxf[sub][g];
        float* obm = ob + HH;
#pragma unroll
        for (int i = 0; i < 9; i++) {
            int t = tq + i * 4;
            if (t < TT) __stcs((float4*)(obm + t * (2 * HH)), mv);
        }
    }
}

extern "C" void kernel_launch(void* const* d_in, const int* in_sizes, int n_in,
                              void* d_out, int out_size) {
    const float* vox   = (const float*)d_in[0];
    const float* Wm    = (const float*)d_in[1];
    const float* b     = (const float*)d_in[2];
    const float* gamma = (const float*)d_in[3];
    const float* beta  = (const float*)d_in[4];
    float* out = (float*)d_out;

    int N = in_sizes[0] / (TT * CC);

    stats_kernel<<<NBS, 256>>>(vox, N);
    fold_kernel<<<1, 288>>>(Wm, b, gamma, beta, N);
    main_kernel<<<(N + 3) / 4, 256>>>(vox, out, N);
}